// round 4
// baseline (speedup 1.0000x reference)
#include <cuda_runtime.h>

#define H_HEADS 4
#define HIDD 256
#define B_SZ 16
#define U_SZ 64
#define T_SZ 128
#define E_DIM 128

// ---------------- scratch (device globals) ----------------
__device__ float g_uq[1024 * 256];   // u-path output (x2u @ Wq + bq)
__device__ float g_kh[2048 * 256];   // t-path output (x2t @ Wk + bk)
__device__ float g_Wq[128 * 256];
__device__ float g_Wk[128 * 256];
__device__ float g_bq[256];
__device__ float g_bk[256];
__device__ float g_hq[4 * 256];

// ============================================================================
// prep: blocks 0-7 -> Wq = uw2 @ fw1[:128]   (64x64 tiles of 128x256)
//       blocks 8-15 -> Wk = tw2 @ fw1[128:]
//       block 16   -> bq, bk(+fb1), hq[4]
// ============================================================================
__global__ __launch_bounds__(256) void prep_kernel(
    const float* __restrict__ uw2, const float* __restrict__ ub2,
    const float* __restrict__ tw2, const float* __restrict__ tb2,
    const float* __restrict__ head_q, const float* __restrict__ fw1,
    const float* __restrict__ fb1)
{
    __shared__ float As[16][65];
    __shared__ float Bs[16][64];
    int blk = blockIdx.x;
    int tid = threadIdx.x;

    if (blk < 16) {
        bool isQ = blk < 8;
        int t = isQ ? blk : blk - 8;
        const float* A  = isQ ? uw2 : tw2;
        const float* Bm = isQ ? fw1 : fw1 + 128 * 256;
        float* C        = isQ ? g_Wq : g_Wk;
        int bm = (t >> 2) * 64, bn = (t & 3) * 64;
        int tm = (tid / 16) * 4, tn = (tid % 16) * 4;
        int arow = tid / 4, ak = (tid % 4) * 4;
        int brow = tid / 16, bcol = (tid % 16) * 4;
        float acc[4][4] = {};
        for (int k0 = 0; k0 < 128; k0 += 16) {
            float4 av = *(const float4*)&A[(bm + arow) * 128 + k0 + ak];
            As[ak + 0][arow] = av.x; As[ak + 1][arow] = av.y;
            As[ak + 2][arow] = av.z; As[ak + 3][arow] = av.w;
            *(float4*)&Bs[brow][bcol] = *(const float4*)&Bm[(k0 + brow) * 256 + bn + bcol];
            __syncthreads();
#pragma unroll
            for (int k = 0; k < 16; k++) {
                float a0 = As[k][tm], a1 = As[k][tm + 1], a2 = As[k][tm + 2], a3 = As[k][tm + 3];
                float4 bv = *(const float4*)&Bs[k][tn];
                acc[0][0] += a0 * bv.x; acc[0][1] += a0 * bv.y; acc[0][2] += a0 * bv.z; acc[0][3] += a0 * bv.w;
                acc[1][0] += a1 * bv.x; acc[1][1] += a1 * bv.y; acc[1][2] += a1 * bv.z; acc[1][3] += a1 * bv.w;
                acc[2][0] += a2 * bv.x; acc[2][1] += a2 * bv.y; acc[2][2] += a2 * bv.z; acc[2][3] += a2 * bv.w;
                acc[3][0] += a3 * bv.x; acc[3][1] += a3 * bv.y; acc[3][2] += a3 * bv.z; acc[3][3] += a3 * bv.w;
            }
            __syncthreads();
        }
#pragma unroll
        for (int i = 0; i < 4; i++)
            *(float4*)&C[(bm + tm + i) * 256 + bn + tn] =
                make_float4(acc[i][0], acc[i][1], acc[i][2], acc[i][3]);
    } else {
        int d = tid;
        float sq = 0.f, sk = 0.f, h0 = 0.f, h1 = 0.f, h2 = 0.f, h3 = 0.f;
        for (int e = 0; e < 128; e++) {
            float fq = fw1[e * 256 + d];
            float fk = fw1[(128 + e) * 256 + d];
            sq += ub2[e] * fq;
            sk += tb2[e] * fk;
            h0 += head_q[e] * fq;
            h1 += head_q[128 + e] * fq;
            h2 += head_q[256 + e] * fq;
            h3 += head_q[384 + e] * fq;
        }
        g_bq[d] = sq;
        g_bk[d] = sk + fb1[d];
        g_hq[d] = h0; g_hq[256 + d] = h1; g_hq[512 + d] = h2; g_hq[768 + d] = h3;
    }
}

// ============================================================================
// fused_mlp: 192 blocks x 256 threads, 16 rows/block.
//   blocks 0-63: u-path (1024 rows)   blocks 64-191: t-path (2048 rows)
//   in(32) -> relu L1(128) -> relu L2(128) -> L3(256, folded Wq/Wk + bias)
//   Activations in smem; weight K-tiles double-buffered through registers.
// ============================================================================
__global__ __launch_bounds__(256) void fused_mlp(
    const float* __restrict__ uav, const float* __restrict__ task,
    const float* __restrict__ uw0, const float* __restrict__ ub0,
    const float* __restrict__ uw1, const float* __restrict__ ub1,
    const float* __restrict__ tw0, const float* __restrict__ tb0,
    const float* __restrict__ tw1, const float* __restrict__ tb1)
{
    __shared__ float x0[16 * 36];    // padded rows (36) -> a-broadcast conflict-free
    __shared__ float x1[16 * 132];
    __shared__ float x2[16 * 132];
    __shared__ float wt[4096];       // weight tile: L1 32x128 / L2 32x128 / L3 16x256

    int tid = threadIdx.x;
    int bid = blockIdx.x;
    bool isU = bid < 64;
    int row0 = isU ? bid * 16 : (bid - 64) * 16;

    const float* in = (isU ? uav : task) + row0 * 32;
    const float* W0 = isU ? uw0 : tw0;
    const float* B0 = isU ? ub0 : tb0;
    const float* W1 = isU ? uw1 : tw1;
    const float* B1 = isU ? ub1 : tb1;
    const float* W3 = isU ? g_Wq : g_Wk;
    const float* B3 = isU ? g_bq : g_bk;
    float* outp = (isU ? g_uq : g_kh) + row0 * 256;

    int r = tid >> 4, c = tid & 15;

    // ---- load x0 (16x32) and W0 (32x128) ----
    if (tid < 128) {
        float4 v = ((const float4*)in)[tid];
        int rr = tid >> 3, c4 = tid & 7;
        *(float4*)&x0[rr * 36 + c4 * 4] = v;
    }
#pragma unroll
    for (int i = 0; i < 4; i++)
        ((float4*)wt)[tid + i * 256] = ((const float4*)W0)[tid + i * 256];
    __syncthreads();

    // prefetch L2 tile 0 while computing L1
    float4 st[4];
#pragma unroll
    for (int i = 0; i < 4; i++) st[i] = ((const float4*)W1)[tid + i * 256];

    // ---- Layer 1: out 16x128, K=32 ----
    {
        float acc[8] = {};
#pragma unroll
        for (int k = 0; k < 32; k++) {
            float a = x0[r * 36 + k];
            float4 w0v = *(const float4*)&wt[k * 128 + c * 8];
            float4 w1v = *(const float4*)&wt[k * 128 + c * 8 + 4];
            acc[0] += a * w0v.x; acc[1] += a * w0v.y; acc[2] += a * w0v.z; acc[3] += a * w0v.w;
            acc[4] += a * w1v.x; acc[5] += a * w1v.y; acc[6] += a * w1v.z; acc[7] += a * w1v.w;
        }
        float4 b0a = *(const float4*)&B0[c * 8];
        float4 b0b = *(const float4*)&B0[c * 8 + 4];
        *(float4*)&x1[r * 132 + c * 8] = make_float4(
            fmaxf(acc[0] + b0a.x, 0.f), fmaxf(acc[1] + b0a.y, 0.f),
            fmaxf(acc[2] + b0a.z, 0.f), fmaxf(acc[3] + b0a.w, 0.f));
        *(float4*)&x1[r * 132 + c * 8 + 4] = make_float4(
            fmaxf(acc[4] + b0b.x, 0.f), fmaxf(acc[5] + b0b.y, 0.f),
            fmaxf(acc[6] + b0b.z, 0.f), fmaxf(acc[7] + b0b.w, 0.f));
    }
    __syncthreads();                       // x1 ready, wt(W0) reads done
#pragma unroll
    for (int i = 0; i < 4; i++) ((float4*)wt)[tid + i * 256] = st[i];

    // ---- Layer 2: out 16x128, K=128, 4 K-tiles of 32 ----
    float acc2[8] = {};
    for (int kt = 0; kt < 4; kt++) {
        __syncthreads();                   // tile ready
        if (kt < 3) {
#pragma unroll
            for (int i = 0; i < 4; i++)
                st[i] = ((const float4*)W1)[(kt + 1) * 1024 + tid + i * 256];
        }
#pragma unroll
        for (int k = 0; k < 32; k++) {
            float a = x1[r * 132 + kt * 32 + k];
            float4 w0v = *(const float4*)&wt[k * 128 + c * 8];
            float4 w1v = *(const float4*)&wt[k * 128 + c * 8 + 4];
            acc2[0] += a * w0v.x; acc2[1] += a * w0v.y; acc2[2] += a * w0v.z; acc2[3] += a * w0v.w;
            acc2[4] += a * w1v.x; acc2[5] += a * w1v.y; acc2[6] += a * w1v.z; acc2[7] += a * w1v.w;
        }
        __syncthreads();                   // reads done
        if (kt < 3) {
#pragma unroll
            for (int i = 0; i < 4; i++) ((float4*)wt)[tid + i * 256] = st[i];
        }
    }
    {
        float4 b1a = *(const float4*)&B1[c * 8];
        float4 b1b = *(const float4*)&B1[c * 8 + 4];
        *(float4*)&x2[r * 132 + c * 8] = make_float4(
            fmaxf(acc2[0] + b1a.x, 0.f), fmaxf(acc2[1] + b1a.y, 0.f),
            fmaxf(acc2[2] + b1a.z, 0.f), fmaxf(acc2[3] + b1a.w, 0.f));
        *(float4*)&x2[r * 132 + c * 8 + 4] = make_float4(
            fmaxf(acc2[4] + b1b.x, 0.f), fmaxf(acc2[5] + b1b.y, 0.f),
            fmaxf(acc2[6] + b1b.z, 0.f), fmaxf(acc2[7] + b1b.w, 0.f));
    }
#pragma unroll
    for (int i = 0; i < 4; i++) st[i] = ((const float4*)W3)[tid + i * 256];
    __syncthreads();                       // x2 ready
#pragma unroll
    for (int i = 0; i < 4; i++) ((float4*)wt)[tid + i * 256] = st[i];

    // ---- Layer 3: out 16x256, K=128, 8 K-tiles of 16 (tile = 16x256) ----
    float acc3[16] = {};
    for (int kt = 0; kt < 8; kt++) {
        __syncthreads();
        if (kt < 7) {
#pragma unroll
            for (int i = 0; i < 4; i++)
                st[i] = ((const float4*)W3)[(kt + 1) * 1024 + tid + i * 256];
        }
#pragma unroll
        for (int k = 0; k < 16; k++) {
            float a = x2[r * 132 + kt * 16 + k];
#pragma unroll
            for (int j = 0; j < 4; j++) {
                float4 wv = *(const float4*)&wt[k * 256 + c * 16 + j * 4];
                acc3[j * 4 + 0] += a * wv.x;
                acc3[j * 4 + 1] += a * wv.y;
                acc3[j * 4 + 2] += a * wv.z;
                acc3[j * 4 + 3] += a * wv.w;
            }
        }
        __syncthreads();
        if (kt < 7) {
#pragma unroll
            for (int i = 0; i < 4; i++) ((float4*)wt)[tid + i * 256] = st[i];
        }
    }
#pragma unroll
    for (int j = 0; j < 4; j++) {
        float4 bv = *(const float4*)&B3[c * 16 + j * 4];
        *(float4*)&outp[r * 256 + c * 16 + j * 4] = make_float4(
            acc3[j * 4 + 0] + bv.x, acc3[j * 4 + 1] + bv.y,
            acc3[j * 4 + 2] + bv.z, acc3[j * 4 + 3] + bv.w);
    }
}

// ============================================================================
// final: logits[b,h,u,t] = fb2 + sum_d relu(uq[b,u,d]+hq[h,d]+kh[b,t,d])*fw2[d]
// grid (2 u-tiles, H, B) = 128 blocks (one wave), 256 threads.
// Thread: 4u x 4t register tile; k in d-major smem (float2 loads, conflict-free).
// ============================================================================
__global__ __launch_bounds__(256) void final_kernel(
    const float* __restrict__ fw2, const float* __restrict__ fb2,
    float* __restrict__ out)
{
    const int DC = 64;
    __shared__ float kd[DC][130];    // [d][t], stride 130
    __shared__ float qs[32 * DC];    // [u][d]
    __shared__ float ws[DC];

    int b = blockIdx.z, h = blockIdx.y, ut = blockIdx.x;
    int tid = threadIdx.x, lane = tid & 31, wrp = tid >> 5;
    int u0 = ut * 32;

    const float* uqp = g_uq + (b * U_SZ + u0) * HIDD;
    const float* khp = g_kh + (b * T_SZ) * HIDD;
    const float* hq  = g_hq + h * HIDD;

    int lt = tid & 127, ldh = tid >> 7;   // kd loader: t index, d-half

    float acc[4][4] = {};

    for (int dc = 0; dc < HIDD; dc += DC) {
        // load k tile (transpose to d-major)
#pragma unroll
        for (int i = 0; i < 8; i++) {
            int d = ldh * 32 + i * 4;
            float4 v = *(const float4*)&khp[lt * HIDD + dc + d];
            kd[d + 0][lt] = v.x; kd[d + 1][lt] = v.y;
            kd[d + 2][lt] = v.z; kd[d + 3][lt] = v.w;
        }
        // load q tile (+ per-head query)
#pragma unroll
        for (int i = 0; i < 2; i++) {
            int idx = tid + i * 256;
            int uu = idx >> 4, d4 = (idx & 15) * 4;
            float4 v  = *(const float4*)&uqp[uu * HIDD + dc + d4];
            float4 hv = *(const float4*)&hq[dc + d4];
            *(float4*)&qs[uu * DC + d4] =
                make_float4(v.x + hv.x, v.y + hv.y, v.z + hv.z, v.w + hv.w);
        }
        if (tid < DC) ws[tid] = fw2[dc + tid];
        __syncthreads();

        const float* q0p = &qs[(wrp * 4 + 0) * DC];
        const float* q1p = &qs[(wrp * 4 + 1) * DC];
        const float* q2p = &qs[(wrp * 4 + 2) * DC];
        const float* q3p = &qs[(wrp * 4 + 3) * DC];

#pragma unroll 4
        for (int d = 0; d < DC; d += 2) {
            float2 wv = *(const float2*)&ws[d];
            float2 q0 = *(const float2*)&q0p[d];
            float2 q1 = *(const float2*)&q1p[d];
            float2 q2 = *(const float2*)&q2p[d];
            float2 q3 = *(const float2*)&q3p[d];
            float2 ka0 = *(const float2*)&kd[d][2 * lane];        // t = 2l, 2l+1   (d)
            float2 kb0 = *(const float2*)&kd[d][2 * lane + 64];   // t = 2l+64,65   (d)
            float2 ka1 = *(const float2*)&kd[d + 1][2 * lane];    // (d+1)
            float2 kb1 = *(const float2*)&kd[d + 1][2 * lane + 64];
#pragma unroll
            for (int i = 0; i < 4; i++) {
                float2 q = (i == 0) ? q0 : (i == 1) ? q1 : (i == 2) ? q2 : q3;
                acc[i][0] += fmaxf(q.x + ka0.x, 0.f) * wv.x + fmaxf(q.y + ka1.x, 0.f) * wv.y;
                acc[i][1] += fmaxf(q.x + ka0.y, 0.f) * wv.x + fmaxf(q.y + ka1.y, 0.f) * wv.y;
                acc[i][2] += fmaxf(q.x + kb0.x, 0.f) * wv.x + fmaxf(q.y + kb1.x, 0.f) * wv.y;
                acc[i][3] += fmaxf(q.x + kb0.y, 0.f) * wv.x + fmaxf(q.y + kb1.y, 0.f) * wv.y;
            }
        }
        __syncthreads();
    }

    float bias = fb2[0];
#pragma unroll
    for (int i = 0; i < 4; i++) {
        int urow = (b * H_HEADS + h) * U_SZ + u0 + wrp * 4 + i;
        float* orow = out + urow * T_SZ;
        *(float2*)&orow[2 * lane]      = make_float2(acc[i][0] + bias, acc[i][1] + bias);
        *(float2*)&orow[2 * lane + 64] = make_float2(acc[i][2] + bias, acc[i][3] + bias);
    }
}

// ---------------- launch ----------------
extern "C" void kernel_launch(void* const* d_in, const int* in_sizes, int n_in,
                              void* d_out, int out_size)
{
    const float* uav    = (const float*)d_in[0];
    const float* task   = (const float*)d_in[1];
    const float* uw0    = (const float*)d_in[2];
    const float* ub0    = (const float*)d_in[3];
    const float* uw1    = (const float*)d_in[4];
    const float* ub1    = (const float*)d_in[5];
    const float* uw2    = (const float*)d_in[6];
    const float* ub2    = (const float*)d_in[7];
    const float* tw0    = (const float*)d_in[8];
    const float* tb0    = (const float*)d_in[9];
    const float* tw1    = (const float*)d_in[10];
    const float* tb1    = (const float*)d_in[11];
    const float* tw2    = (const float*)d_in[12];
    const float* tb2    = (const float*)d_in[13];
    const float* head_q = (const float*)d_in[14];
    const float* fw1    = (const float*)d_in[15];
    const float* fb1    = (const float*)d_in[16];
    const float* fw2    = (const float*)d_in[17];
    const float* fb2    = (const float*)d_in[18];
    float* out = (float*)d_out;

    prep_kernel<<<17, 256>>>(uw2, ub2, tw2, tb2, head_q, fw1, fb1);
    fused_mlp<<<192, 256>>>(uav, task, uw0, ub0, uw1, ub1, tw0, tb0, tw1, tb1);
    final_kernel<<<dim3(2, H_HEADS, B_SZ), 256>>>(fw2, fb2, out);
}

// round 6
// speedup vs baseline: 2.3134x; 2.3134x over previous
#include <cuda_runtime.h>

#define H_HEADS 4
#define HIDD 256
#define B_SZ 16
#define U_SZ 64
#define T_SZ 128
#define E_DIM 128

// ---------------- scratch (device globals) ----------------
__device__ float g_u1[1024 * 128];
__device__ float g_u2[1024 * 128];
__device__ float g_uq[1024 * 256];
__device__ float g_t1[2048 * 128];
__device__ float g_t2[2048 * 128];
__device__ float g_kh[2048 * 256];
__device__ float g_Wq[128 * 256];
__device__ float g_Wk[128 * 256];
__device__ float g_bq[256];
__device__ float g_bk[256];
__device__ float g_hq[4 * 256];

// ---------------- 64x64 GEMM tile (device fn), row-major, K%16==0 ----------------
// C[bm:bm+64, bn:bn+64] = op(A[.,K] @ B[.,N] + bias)
__device__ __forceinline__ void gemm_tile(
    const float* __restrict__ A, const float* __restrict__ B,
    const float* __restrict__ bias, float* __restrict__ C,
    int N, int K, int bm, int bn, bool relu,
    float* As /*16*65*/, float* Bs /*16*64*/)
{
    int tid = threadIdx.x;
    int tm = (tid / 16) * 4, tn = (tid % 16) * 4;
    int arow = tid / 4, ak = (tid % 4) * 4;
    int brow = tid / 16, bcol = (tid % 16) * 4;

    float acc[4][4] = {};

    for (int k0 = 0; k0 < K; k0 += 16) {
        float4 av = *(const float4*)&A[(bm + arow) * K + k0 + ak];
        As[(ak + 0) * 65 + arow] = av.x;
        As[(ak + 1) * 65 + arow] = av.y;
        As[(ak + 2) * 65 + arow] = av.z;
        As[(ak + 3) * 65 + arow] = av.w;
        *(float4*)&Bs[brow * 64 + bcol] = *(const float4*)&B[(k0 + brow) * N + bn + bcol];
        __syncthreads();
#pragma unroll
        for (int k = 0; k < 16; k++) {
            float a0 = As[k * 65 + tm + 0], a1 = As[k * 65 + tm + 1];
            float a2 = As[k * 65 + tm + 2], a3 = As[k * 65 + tm + 3];
            float4 bv = *(const float4*)&Bs[k * 64 + tn];
            acc[0][0] += a0 * bv.x; acc[0][1] += a0 * bv.y; acc[0][2] += a0 * bv.z; acc[0][3] += a0 * bv.w;
            acc[1][0] += a1 * bv.x; acc[1][1] += a1 * bv.y; acc[1][2] += a1 * bv.z; acc[1][3] += a1 * bv.w;
            acc[2][0] += a2 * bv.x; acc[2][1] += a2 * bv.y; acc[2][2] += a2 * bv.z; acc[2][3] += a2 * bv.w;
            acc[3][0] += a3 * bv.x; acc[3][1] += a3 * bv.y; acc[3][2] += a3 * bv.z; acc[3][3] += a3 * bv.w;
        }
        __syncthreads();
    }

    float b0 = 0.f, b1 = 0.f, b2 = 0.f, b3 = 0.f;
    if (bias) {
        b0 = bias[bn + tn + 0]; b1 = bias[bn + tn + 1];
        b2 = bias[bn + tn + 2]; b3 = bias[bn + tn + 3];
    }
#pragma unroll
    for (int i = 0; i < 4; i++) {
        float4 o = make_float4(acc[i][0] + b0, acc[i][1] + b1, acc[i][2] + b2, acc[i][3] + b3);
        if (relu) {
            o.x = fmaxf(o.x, 0.f); o.y = fmaxf(o.y, 0.f);
            o.z = fmaxf(o.z, 0.f); o.w = fmaxf(o.w, 0.f);
        }
        *(float4*)&C[(bm + tm + i) * N + bn + tn] = o;
    }
}

// ============================================================================
// K1: 114 blocks. 0-31 u-L1 | 32-95 t-L1 | 96-103 Wq fold | 104-111 Wk fold
//     112: bq + hq[4]   113: bk(+fb1)
// ============================================================================
__global__ __launch_bounds__(256) void k_stage1(
    const float* __restrict__ uav, const float* __restrict__ task,
    const float* __restrict__ uw0, const float* __restrict__ ub0,
    const float* __restrict__ tw0, const float* __restrict__ tb0,
    const float* __restrict__ uw2, const float* __restrict__ tw2,
    const float* __restrict__ fw1, const float* __restrict__ ub2,
    const float* __restrict__ tb2, const float* __restrict__ head_q,
    const float* __restrict__ fb1)
{
    __shared__ float As[16 * 65];
    __shared__ float Bs[16 * 64];
    int blk = blockIdx.x;

    if (blk < 32) {
        gemm_tile(uav, uw0, ub0, g_u1, 128, 32, (blk >> 1) * 64, (blk & 1) * 64, true, As, Bs);
    } else if (blk < 96) {
        int i = blk - 32;
        gemm_tile(task, tw0, tb0, g_t1, 128, 32, (i >> 1) * 64, (i & 1) * 64, true, As, Bs);
    } else if (blk < 104) {
        int i = blk - 96;
        gemm_tile(uw2, fw1, nullptr, g_Wq, 256, 128, (i >> 2) * 64, (i & 3) * 64, false, As, Bs);
    } else if (blk < 112) {
        int i = blk - 104;
        gemm_tile(tw2, fw1 + 128 * 256, nullptr, g_Wk, 256, 128, (i >> 2) * 64, (i & 3) * 64, false, As, Bs);
    } else if (blk == 112) {
        int d = threadIdx.x;
        float sq = 0.f, h0 = 0.f, h1 = 0.f, h2 = 0.f, h3 = 0.f;
#pragma unroll 8
        for (int e = 0; e < 128; e++) {
            float fq = fw1[e * HIDD + d];
            sq += ub2[e] * fq;
            h0 += head_q[e] * fq;
            h1 += head_q[128 + e] * fq;
            h2 += head_q[256 + e] * fq;
            h3 += head_q[384 + e] * fq;
        }
        g_bq[d] = sq;
        g_hq[d] = h0; g_hq[256 + d] = h1; g_hq[512 + d] = h2; g_hq[768 + d] = h3;
    } else {
        int d = threadIdx.x;
        float sk = 0.f;
#pragma unroll 8
        for (int e = 0; e < 128; e++) sk += tb2[e] * fw1[(128 + e) * HIDD + d];
        g_bk[d] = sk + fb1[d];
    }
}

// ============================================================================
// K2: 96 blocks. 0-31 u-L2 | 32-95 t-L2   (K=128, relu)
// ============================================================================
__global__ __launch_bounds__(256) void k_stage2(
    const float* __restrict__ uw1, const float* __restrict__ ub1,
    const float* __restrict__ tw1, const float* __restrict__ tb1)
{
    __shared__ float As[16 * 65];
    __shared__ float Bs[16 * 64];
    int blk = blockIdx.x;
    if (blk < 32) {
        gemm_tile(g_u1, uw1, ub1, g_u2, 128, 128, (blk >> 1) * 64, (blk & 1) * 64, true, As, Bs);
    } else {
        int i = blk - 32;
        gemm_tile(g_t1, tw1, tb1, g_t2, 128, 128, (i >> 1) * 64, (i & 1) * 64, true, As, Bs);
    }
}

// ============================================================================
// K3: 192 blocks. 0-63 u-L3 (uq) | 64-191 t-L3 (kh)   (N=256, K=128, bias, no relu)
// ============================================================================
__global__ __launch_bounds__(256) void k_stage3()
{
    __shared__ float As[16 * 65];
    __shared__ float Bs[16 * 64];
    int blk = blockIdx.x;
    if (blk < 64) {
        gemm_tile(g_u2, g_Wq, g_bq, g_uq, 256, 128, (blk >> 2) * 64, (blk & 3) * 64, false, As, Bs);
    } else {
        int i = blk - 64;
        gemm_tile(g_t2, g_Wk, g_bk, g_kh, 256, 128, (i >> 2) * 64, (i & 3) * 64, false, As, Bs);
    }
}

// ============================================================================
// final: logits[b,h,u,t] = fb2 + sum_d relu(uq[b,u,d]+hq[h,d]+kh[b,t,d])*fw2[d]
// grid (2 u-tiles, H, B) = 128 blocks (one wave), 256 threads.
// Thread: 4u x 4t register tile; k in d-major smem (float2 loads, conflict-free).
// ============================================================================
__global__ __launch_bounds__(256) void final_kernel(
    const float* __restrict__ fw2, const float* __restrict__ fb2,
    float* __restrict__ out)
{
    const int DC = 64;
    __shared__ float kd[DC][130];
    __shared__ float qs[32 * DC];
    __shared__ float ws[DC];

    int b = blockIdx.z, h = blockIdx.y, ut = blockIdx.x;
    int tid = threadIdx.x, lane = tid & 31, wrp = tid >> 5;
    int u0 = ut * 32;

    const float* uqp = g_uq + (b * U_SZ + u0) * HIDD;
    const float* khp = g_kh + (b * T_SZ) * HIDD;
    const float* hq  = g_hq + h * HIDD;

    int lt = tid & 127, ldh = tid >> 7;

    float acc[4][4] = {};

    for (int dc = 0; dc < HIDD; dc += DC) {
#pragma unroll
        for (int i = 0; i < 8; i++) {
            int d = ldh * 32 + i * 4;
            float4 v = *(const float4*)&khp[lt * HIDD + dc + d];
            kd[d + 0][lt] = v.x; kd[d + 1][lt] = v.y;
            kd[d + 2][lt] = v.z; kd[d + 3][lt] = v.w;
        }
#pragma unroll
        for (int i = 0; i < 2; i++) {
            int idx = tid + i * 256;
            int uu = idx >> 4, d4 = (idx & 15) * 4;
            float4 v  = *(const float4*)&uqp[uu * HIDD + dc + d4];
            float4 hv = *(const float4*)&hq[dc + d4];
            *(float4*)&qs[uu * DC + d4] =
                make_float4(v.x + hv.x, v.y + hv.y, v.z + hv.z, v.w + hv.w);
        }
        if (tid < DC) ws[tid] = fw2[dc + tid];
        __syncthreads();

        const float* q0p = &qs[(wrp * 4 + 0) * DC];
        const float* q1p = &qs[(wrp * 4 + 1) * DC];
        const float* q2p = &qs[(wrp * 4 + 2) * DC];
        const float* q3p = &qs[(wrp * 4 + 3) * DC];

#pragma unroll 4
        for (int d = 0; d < DC; d += 2) {
            float2 wv = *(const float2*)&ws[d];
            float2 q0 = *(const float2*)&q0p[d];
            float2 q1 = *(const float2*)&q1p[d];
            float2 q2 = *(const float2*)&q2p[d];
            float2 q3 = *(const float2*)&q3p[d];
            float2 ka0 = *(const float2*)&kd[d][2 * lane];
            float2 kb0 = *(const float2*)&kd[d][2 * lane + 64];
            float2 ka1 = *(const float2*)&kd[d + 1][2 * lane];
            float2 kb1 = *(const float2*)&kd[d + 1][2 * lane + 64];
#pragma unroll
            for (int i = 0; i < 4; i++) {
                float2 q = (i == 0) ? q0 : (i == 1) ? q1 : (i == 2) ? q2 : q3;
                acc[i][0] += fmaxf(q.x + ka0.x, 0.f) * wv.x + fmaxf(q.y + ka1.x, 0.f) * wv.y;
                acc[i][1] += fmaxf(q.x + ka0.y, 0.f) * wv.x + fmaxf(q.y + ka1.y, 0.f) * wv.y;
                acc[i][2] += fmaxf(q.x + kb0.x, 0.f) * wv.x + fmaxf(q.y + kb1.x, 0.f) * wv.y;
                acc[i][3] += fmaxf(q.x + kb0.y, 0.f) * wv.x + fmaxf(q.y + kb1.y, 0.f) * wv.y;
            }
        }
        __syncthreads();
    }

    float bias = fb2[0];
#pragma unroll
    for (int i = 0; i < 4; i++) {
        int urow = (b * H_HEADS + h) * U_SZ + u0 + wrp * 4 + i;
        float* orow = out + urow * T_SZ;
        *(float2*)&orow[2 * lane]      = make_float2(acc[i][0] + bias, acc[i][1] + bias);
        *(float2*)&orow[2 * lane + 64] = make_float2(acc[i][2] + bias, acc[i][3] + bias);
    }
}

// ---------------- launch ----------------
extern "C" void kernel_launch(void* const* d_in, const int* in_sizes, int n_in,
                              void* d_out, int out_size)
{
    const float* uav    = (const float*)d_in[0];
    const float* task   = (const float*)d_in[1];
    const float* uw0    = (const float*)d_in[2];
    const float* ub0    = (const float*)d_in[3];
    const float* uw1    = (const float*)d_in[4];
    const float* ub1    = (const float*)d_in[5];
    const float* uw2    = (const float*)d_in[6];
    const float* ub2    = (const float*)d_in[7];
    const float* tw0    = (const float*)d_in[8];
    const float* tb0    = (const float*)d_in[9];
    const float* tw1    = (const float*)d_in[10];
    const float* tb1    = (const float*)d_in[11];
    const float* tw2    = (const float*)d_in[12];
    const float* tb2    = (const float*)d_in[13];
    const float* head_q = (const float*)d_in[14];
    const float* fw1    = (const float*)d_in[15];
    const float* fb1    = (const float*)d_in[16];
    const float* fw2    = (const float*)d_in[17];
    const float* fb2    = (const float*)d_in[18];
    float* out = (float*)d_out;

    k_stage1<<<114, 256>>>(uav, task, uw0, ub0, tw0, tb0, uw2, tw2, fw1, ub2, tb2, head_q, fb1);
    k_stage2<<<96, 256>>>(uw1, ub1, tw1, tb1);
    k_stage3<<<192, 256>>>();
    final_kernel<<<dim3(2, H_HEADS, B_SZ), 256>>>(fw2, fb2, out);
}

// round 8
// speedup vs baseline: 2.4632x; 1.0647x over previous
#include <cuda_runtime.h>

#define H_HEADS 4
#define HIDD 256
#define B_SZ 16
#define U_SZ 64
#define T_SZ 128
#define E_DIM 128

// ---------------- packed f32x2 helpers ----------------
#define ADD2(out, a, b) \
    asm("add.rn.f32x2 %0, %1, %2;" : "=l"(out) : "l"(a), "l"(b))
#define FMA2(out, a, b, c) \
    asm("fma.rn.f32x2 %0, %1, %2, %3;" : "=l"(out) : "l"(a), "l"(b), "l"(c))
#define UNPACK2(lo, hi, v) \
    asm("mov.b64 {%0, %1}, %2;" : "=f"(lo), "=f"(hi) : "l"(v))
#define PACK2(v, lo, hi) \
    asm("mov.b64 %0, {%1, %2};" : "=l"(v) : "f"(lo), "f"(hi))

// ---------------- scratch (device globals) ----------------
__device__ float g_u1[1024 * 128];
__device__ float g_u2[1024 * 128];
__device__ float g_uq[1024 * 256];
__device__ float g_t1[2048 * 128];
__device__ float g_t2[2048 * 128];
__device__ float g_kh[2048 * 256];
__device__ float g_Wq[128 * 256];
__device__ float g_Wk[128 * 256];
__device__ float g_bq[256];
__device__ float g_bk[256];
__device__ float g_hq[4 * 256];

// ---------------- 64x64 GEMM tile (device fn), row-major, K%16==0 ----------------
// As row-major [16][68] -> A-fragment read is a single LDS.128.
__device__ __forceinline__ void gemm_tile(
    const float* __restrict__ A, const float* __restrict__ B,
    const float* __restrict__ bias, float* __restrict__ C,
    int N, int K, int bm, int bn, bool relu,
    float* As /*16*68*/, float* Bs /*16*64*/)
{
    int tid = threadIdx.x;
    int tm = (tid / 16) * 4, tn = (tid % 16) * 4;
    int arow = tid / 4, ak = (tid % 4) * 4;
    int brow = tid / 16, bcol = (tid % 16) * 4;

    float acc[4][4] = {};

    for (int k0 = 0; k0 < K; k0 += 16) {
        float4 av = *(const float4*)&A[(bm + arow) * K + k0 + ak];
        As[(ak + 0) * 68 + arow] = av.x;
        As[(ak + 1) * 68 + arow] = av.y;
        As[(ak + 2) * 68 + arow] = av.z;
        As[(ak + 3) * 68 + arow] = av.w;
        *(float4*)&Bs[brow * 64 + bcol] = *(const float4*)&B[(k0 + brow) * N + bn + bcol];
        __syncthreads();
#pragma unroll
        for (int k = 0; k < 16; k++) {
            float4 a = *(const float4*)&As[k * 68 + tm];
            float4 bv = *(const float4*)&Bs[k * 64 + tn];
            acc[0][0] += a.x * bv.x; acc[0][1] += a.x * bv.y; acc[0][2] += a.x * bv.z; acc[0][3] += a.x * bv.w;
            acc[1][0] += a.y * bv.x; acc[1][1] += a.y * bv.y; acc[1][2] += a.y * bv.z; acc[1][3] += a.y * bv.w;
            acc[2][0] += a.z * bv.x; acc[2][1] += a.z * bv.y; acc[2][2] += a.z * bv.z; acc[2][3] += a.z * bv.w;
            acc[3][0] += a.w * bv.x; acc[3][1] += a.w * bv.y; acc[3][2] += a.w * bv.z; acc[3][3] += a.w * bv.w;
        }
        __syncthreads();
    }

    float b0 = 0.f, b1 = 0.f, b2 = 0.f, b3 = 0.f;
    if (bias) {
        b0 = bias[bn + tn + 0]; b1 = bias[bn + tn + 1];
        b2 = bias[bn + tn + 2]; b3 = bias[bn + tn + 3];
    }
#pragma unroll
    for (int i = 0; i < 4; i++) {
        float4 o = make_float4(acc[i][0] + b0, acc[i][1] + b1, acc[i][2] + b2, acc[i][3] + b3);
        if (relu) {
            o.x = fmaxf(o.x, 0.f); o.y = fmaxf(o.y, 0.f);
            o.z = fmaxf(o.z, 0.f); o.w = fmaxf(o.w, 0.f);
        }
        *(float4*)&C[(bm + tm + i) * N + bn + tn] = o;
    }
}

// ============================================================================
// K1: 114 blocks. 0-31 u-L1 | 32-95 t-L1 | 96-103 Wq fold | 104-111 Wk fold
//     112: bq + hq[4]   113: bk(+fb1)
// ============================================================================
__global__ __launch_bounds__(256) void k_stage1(
    const float* __restrict__ uav, const float* __restrict__ task,
    const float* __restrict__ uw0, const float* __restrict__ ub0,
    const float* __restrict__ tw0, const float* __restrict__ tb0,
    const float* __restrict__ uw2, const float* __restrict__ tw2,
    const float* __restrict__ fw1, const float* __restrict__ ub2,
    const float* __restrict__ tb2, const float* __restrict__ head_q,
    const float* __restrict__ fb1)
{
    __shared__ float As[16 * 68];
    __shared__ float Bs[16 * 64];
    int blk = blockIdx.x;

    if (blk < 32) {
        gemm_tile(uav, uw0, ub0, g_u1, 128, 32, (blk >> 1) * 64, (blk & 1) * 64, true, As, Bs);
    } else if (blk < 96) {
        int i = blk - 32;
        gemm_tile(task, tw0, tb0, g_t1, 128, 32, (i >> 1) * 64, (i & 1) * 64, true, As, Bs);
    } else if (blk < 104) {
        int i = blk - 96;
        gemm_tile(uw2, fw1, nullptr, g_Wq, 256, 128, (i >> 2) * 64, (i & 3) * 64, false, As, Bs);
    } else if (blk < 112) {
        int i = blk - 104;
        gemm_tile(tw2, fw1 + 128 * 256, nullptr, g_Wk, 256, 128, (i >> 2) * 64, (i & 3) * 64, false, As, Bs);
    } else if (blk == 112) {
        int d = threadIdx.x;
        float sq = 0.f, h0 = 0.f, h1 = 0.f, h2 = 0.f, h3 = 0.f;
#pragma unroll 8
        for (int e = 0; e < 128; e++) {
            float fq = fw1[e * HIDD + d];
            sq += ub2[e] * fq;
            h0 += head_q[e] * fq;
            h1 += head_q[128 + e] * fq;
            h2 += head_q[256 + e] * fq;
            h3 += head_q[384 + e] * fq;
        }
        g_bq[d] = sq;
        g_hq[d] = h0; g_hq[256 + d] = h1; g_hq[512 + d] = h2; g_hq[768 + d] = h3;
    } else {
        int d = threadIdx.x;
        float sk = 0.f;
#pragma unroll 8
        for (int e = 0; e < 128; e++) sk += tb2[e] * fw1[(128 + e) * HIDD + d];
        g_bk[d] = sk + fb1[d];
    }
}

// ============================================================================
// K2: 96 blocks. 0-31 u-L2 | 32-95 t-L2   (K=128, relu)
// ============================================================================
__global__ __launch_bounds__(256) void k_stage2(
    const float* __restrict__ uw1, const float* __restrict__ ub1,
    const float* __restrict__ tw1, const float* __restrict__ tb1)
{
    __shared__ float As[16 * 68];
    __shared__ float Bs[16 * 64];
    int blk = blockIdx.x;
    if (blk < 32) {
        gemm_tile(g_u1, uw1, ub1, g_u2, 128, 128, (blk >> 1) * 64, (blk & 1) * 64, true, As, Bs);
    } else {
        int i = blk - 32;
        gemm_tile(g_t1, tw1, tb1, g_t2, 128, 128, (i >> 1) * 64, (i & 1) * 64, true, As, Bs);
    }
}

// ============================================================================
// K3: 192 blocks. 0-63 u-L3 (uq) | 64-191 t-L3 (kh)   (N=256, K=128, bias)
// ============================================================================
__global__ __launch_bounds__(256) void k_stage3()
{
    __shared__ float As[16 * 68];
    __shared__ float Bs[16 * 64];
    int blk = blockIdx.x;
    if (blk < 64) {
        gemm_tile(g_u2, g_Wq, g_bq, g_uq, 256, 128, (blk >> 2) * 64, (blk & 3) * 64, false, As, Bs);
    } else {
        int i = blk - 64;
        gemm_tile(g_t2, g_Wk, g_bk, g_kh, 256, 128, (i >> 2) * 64, (i & 3) * 64, false, As, Bs);
    }
}

// ============================================================================
// final: logits[b,h,u,t] = fb2 + sum_d relu(uq[b,u,d]+hq[h,d]+kh[b,t,d])*fw2[d]
// grid (2, H, B) = 128 blocks, 512 threads (16 warps/SM).
// Packed f32x2: k-tile stored t-major (ks[t][66]) so every LDS.64 is a (d,d+1)
// pair; ADD2 + 2x FMNMX + FMA2 per 2 d. Thread tile 2u x 4t.
// ============================================================================
__global__ __launch_bounds__(512) void final_kernel(
    const float* __restrict__ fw2, const float* __restrict__ fb2,
    float* __restrict__ out)
{
    const int DC = 64;
    __shared__ float ks[T_SZ * 66];   // [t][d], stride 66: conflict-free LDS.64
    __shared__ float qs[32 * DC];     // [u][d]
    __shared__ float ws[DC];

    int b = blockIdx.z, h = blockIdx.y, ut = blockIdx.x;
    int tid = threadIdx.x, lane = tid & 31, wrp = tid >> 5;
    int u0 = ut * 32;

    const float* uqp = g_uq + (b * U_SZ + u0) * HIDD;
    const float* khp = g_kh + (b * T_SZ) * HIDD;
    const float* hq  = g_hq + h * HIDD;

    // compute-phase mapping
    int uu = (wrp >> 1) * 4 + (lane >> 4) * 2;        // even u in 0..30
    int tA = (wrp & 1) * 64 + (lane & 15);            // base t

    // loader mapping for ks
    int lt = tid & 127, dseg = (tid >> 7) * 16;

    unsigned long long acc[2][4] = {};                // packed (d,d+1) accumulators

    for (int dc = 0; dc < HIDD; dc += DC) {
        // ---- load k tile -> t-major [t][66] ----
#pragma unroll
        for (int i = 0; i < 4; i++) {
            float4 v = *(const float4*)&khp[lt * HIDD + dc + dseg + i * 4];
            float* dst = &ks[lt * 66 + dseg + i * 4];
            *(float2*)(dst)     = make_float2(v.x, v.y);
            *(float2*)(dst + 2) = make_float2(v.z, v.w);
        }
        // ---- load q tile (+ per-head query) ----
        {
            int uq_r = tid >> 4, d4 = (tid & 15) * 4;
            float4 v  = *(const float4*)&uqp[uq_r * HIDD + dc + d4];
            float4 hv = *(const float4*)&hq[dc + d4];
            *(float4*)&qs[uq_r * DC + d4] =
                make_float4(v.x + hv.x, v.y + hv.y, v.z + hv.z, v.w + hv.w);
        }
        if (tid < DC) ws[tid] = fw2[dc + tid];
        __syncthreads();

        const float* qp0 = qs + uu * DC;
        const float* qp1 = qs + (uu + 1) * DC;
        const float* kp0 = ks + tA * 66;
        const float* kp1 = ks + (tA + 16) * 66;
        const float* kp2 = ks + (tA + 32) * 66;
        const float* kp3 = ks + (tA + 48) * 66;

#pragma unroll 4
        for (int d = 0; d < DC; d += 2) {
            unsigned long long W  = *(const unsigned long long*)(ws + d);
            unsigned long long Q0 = *(const unsigned long long*)(qp0 + d);
            unsigned long long Q1 = *(const unsigned long long*)(qp1 + d);
            unsigned long long K0 = *(const unsigned long long*)(kp0 + d);
            unsigned long long K1 = *(const unsigned long long*)(kp1 + d);
            unsigned long long K2 = *(const unsigned long long*)(kp2 + d);
            unsigned long long K3 = *(const unsigned long long*)(kp3 + d);

#define RELU_FMA(ACC, Q, K)                                     \
            {                                                   \
                unsigned long long s_, r_; float lo_, hi_;      \
                ADD2(s_, Q, K);                                 \
                UNPACK2(lo_, hi_, s_);                          \
                lo_ = fmaxf(lo_, 0.f);                          \
                hi_ = fmaxf(hi_, 0.f);                          \
                PACK2(r_, lo_, hi_);                            \
                FMA2(ACC, r_, W, ACC);                          \
            }
            RELU_FMA(acc[0][0], Q0, K0);
            RELU_FMA(acc[0][1], Q0, K1);
            RELU_FMA(acc[0][2], Q0, K2);
            RELU_FMA(acc[0][3], Q0, K3);
            RELU_FMA(acc[1][0], Q1, K0);
            RELU_FMA(acc[1][1], Q1, K1);
            RELU_FMA(acc[1][2], Q1, K2);
            RELU_FMA(acc[1][3], Q1, K3);
#undef RELU_FMA
        }
        __syncthreads();
    }

    float bias = fb2[0];
#pragma unroll
    for (int i = 0; i < 2; i++) {
        int urow = (b * H_HEADS + h) * U_SZ + u0 + uu + i;
        float* orow = out + urow * T_SZ;
#pragma unroll
        for (int j = 0; j < 4; j++) {
            float lo, hi;
            UNPACK2(lo, hi, acc[i][j]);
            orow[tA + j * 16] = lo + hi + bias;
        }
    }
}

// ---------------- launch ----------------
extern "C" void kernel_launch(void* const* d_in, const int* in_sizes, int n_in,
                              void* d_out, int out_size)
{
    const float* uav    = (const float*)d_in[0];
    const float* task   = (const float*)d_in[1];
    const float* uw0    = (const float*)d_in[2];
    const float* ub0    = (const float*)d_in[3];
    const float* uw1    = (const float*)d_in[4];
    const float* ub1    = (const float*)d_in[5];
    const float* uw2    = (const float*)d_in[6];
    const float* ub2    = (const float*)d_in[7];
    const float* tw0    = (const float*)d_in[8];
    const float* tb0    = (const float*)d_in[9];
    const float* tw1    = (const float*)d_in[10];
    const float* tb1    = (const float*)d_in[11];
    const float* tw2    = (const float*)d_in[12];
    const float* tb2    = (const float*)d_in[13];
    const float* head_q = (const float*)d_in[14];
    const float* fw1    = (const float*)d_in[15];
    const float* fb1    = (const float*)d_in[16];
    const float* fw2    = (const float*)d_in[17];
    const float* fb2    = (const float*)d_in[18];
    float* out = (float*)d_out;

    k_stage1<<<114, 256>>>(uav, task, uw0, ub0, tw0, tb0, uw2, tw2, fw1, ub2, tb2, head_q, fb1);
    k_stage2<<<96, 256>>>(uw1, ub1, tw1, tb1);
    k_stage3<<<192, 256>>>();
    final_kernel<<<dim3(2, H_HEADS, B_SZ), 512>>>(fw2, fb2, out);
}

// round 10
// speedup vs baseline: 2.7000x; 1.0961x over previous
#include <cuda_runtime.h>

#define H_HEADS 4
#define HIDD 256
#define B_SZ 16
#define U_SZ 64
#define T_SZ 128
#define E_DIM 128

typedef unsigned long long ull;

// ---------------- packed f32x2 helpers ----------------
#define ADD2(out, a, b) \
    asm("add.rn.f32x2 %0, %1, %2;" : "=l"(out) : "l"(a), "l"(b))
#define FMA2(out, a, b, c) \
    asm("fma.rn.f32x2 %0, %1, %2, %3;" : "=l"(out) : "l"(a), "l"(b), "l"(c))
#define UNPACK2(lo, hi, v) \
    asm("mov.b64 {%0, %1}, %2;" : "=f"(lo), "=f"(hi) : "l"(v))
#define PACK2(v, lo, hi) \
    asm("mov.b64 %0, {%1, %2};" : "=l"(v) : "f"(lo), "f"(hi))

// ---------------- scratch (device globals) ----------------
__device__ float g_u1[1024 * 128];
__device__ float g_u2[1024 * 128];
__device__ float g_uq[1024 * 256];
__device__ float g_t1[2048 * 128];
__device__ float g_t2[2048 * 128];
__device__ float g_kh[2048 * 256];
__device__ float g_Wq[128 * 256];
__device__ float g_Wk[128 * 256];
__device__ float g_bq[256];
__device__ float g_bk[256];
__device__ float g_hq[4 * 256];

// ---------------- 64x64 GEMM tile (device fn), row-major, K%16==0 ----------------
__device__ __forceinline__ void gemm_tile(
    const float* __restrict__ A, const float* __restrict__ B,
    const float* __restrict__ bias, float* __restrict__ C,
    int N, int K, int bm, int bn, bool relu,
    float* As /*16*68*/, float* Bs /*16*64*/)
{
    int tid = threadIdx.x;
    int tm = (tid / 16) * 4, tn = (tid % 16) * 4;
    int arow = tid / 4, ak = (tid % 4) * 4;
    int brow = tid / 16, bcol = (tid % 16) * 4;

    float acc[4][4] = {};

    for (int k0 = 0; k0 < K; k0 += 16) {
        float4 av = *(const float4*)&A[(bm + arow) * K + k0 + ak];
        As[(ak + 0) * 68 + arow] = av.x;
        As[(ak + 1) * 68 + arow] = av.y;
        As[(ak + 2) * 68 + arow] = av.z;
        As[(ak + 3) * 68 + arow] = av.w;
        *(float4*)&Bs[brow * 64 + bcol] = *(const float4*)&B[(k0 + brow) * N + bn + bcol];
        __syncthreads();
#pragma unroll
        for (int k = 0; k < 16; k++) {
            float4 a = *(const float4*)&As[k * 68 + tm];
            float4 bv = *(const float4*)&Bs[k * 64 + tn];
            acc[0][0] += a.x * bv.x; acc[0][1] += a.x * bv.y; acc[0][2] += a.x * bv.z; acc[0][3] += a.x * bv.w;
            acc[1][0] += a.y * bv.x; acc[1][1] += a.y * bv.y; acc[1][2] += a.y * bv.z; acc[1][3] += a.y * bv.w;
            acc[2][0] += a.z * bv.x; acc[2][1] += a.z * bv.y; acc[2][2] += a.z * bv.z; acc[2][3] += a.z * bv.w;
            acc[3][0] += a.w * bv.x; acc[3][1] += a.w * bv.y; acc[3][2] += a.w * bv.z; acc[3][3] += a.w * bv.w;
        }
        __syncthreads();
    }

    float b0 = 0.f, b1 = 0.f, b2 = 0.f, b3 = 0.f;
    if (bias) {
        b0 = bias[bn + tn + 0]; b1 = bias[bn + tn + 1];
        b2 = bias[bn + tn + 2]; b3 = bias[bn + tn + 3];
    }
#pragma unroll
    for (int i = 0; i < 4; i++) {
        float4 o = make_float4(acc[i][0] + b0, acc[i][1] + b1, acc[i][2] + b2, acc[i][3] + b3);
        if (relu) {
            o.x = fmaxf(o.x, 0.f); o.y = fmaxf(o.y, 0.f);
            o.z = fmaxf(o.z, 0.f); o.w = fmaxf(o.w, 0.f);
        }
        *(float4*)&C[(bm + tm + i) * N + bn + tn] = o;
    }
}

// ============================================================================
// K1: 114 blocks. 0-31 u-L1 | 32-95 t-L1 | 96-103 Wq fold | 104-111 Wk fold
//     112: bq + hq[4]   113: bk(+fb1)
// ============================================================================
__global__ __launch_bounds__(256) void k_stage1(
    const float* __restrict__ uav, const float* __restrict__ task,
    const float* __restrict__ uw0, const float* __restrict__ ub0,
    const float* __restrict__ tw0, const float* __restrict__ tb0,
    const float* __restrict__ uw2, const float* __restrict__ tw2,
    const float* __restrict__ fw1, const float* __restrict__ ub2,
    const float* __restrict__ tb2, const float* __restrict__ head_q,
    const float* __restrict__ fb1)
{
    __shared__ float As[16 * 68];
    __shared__ float Bs[16 * 64];
    int blk = blockIdx.x;

    if (blk < 32) {
        gemm_tile(uav, uw0, ub0, g_u1, 128, 32, (blk >> 1) * 64, (blk & 1) * 64, true, As, Bs);
    } else if (blk < 96) {
        int i = blk - 32;
        gemm_tile(task, tw0, tb0, g_t1, 128, 32, (i >> 1) * 64, (i & 1) * 64, true, As, Bs);
    } else if (blk < 104) {
        int i = blk - 96;
        gemm_tile(uw2, fw1, nullptr, g_Wq, 256, 128, (i >> 2) * 64, (i & 3) * 64, false, As, Bs);
    } else if (blk < 112) {
        int i = blk - 104;
        gemm_tile(tw2, fw1 + 128 * 256, nullptr, g_Wk, 256, 128, (i >> 2) * 64, (i & 3) * 64, false, As, Bs);
    } else if (blk == 112) {
        int d = threadIdx.x;
        float sq = 0.f, h0 = 0.f, h1 = 0.f, h2 = 0.f, h3 = 0.f;
#pragma unroll 8
        for (int e = 0; e < 128; e++) {
            float fq = fw1[e * HIDD + d];
            sq += ub2[e] * fq;
            h0 += head_q[e] * fq;
            h1 += head_q[128 + e] * fq;
            h2 += head_q[256 + e] * fq;
            h3 += head_q[384 + e] * fq;
        }
        g_bq[d] = sq;
        g_hq[d] = h0; g_hq[256 + d] = h1; g_hq[512 + d] = h2; g_hq[768 + d] = h3;
    } else {
        int d = threadIdx.x;
        float sk = 0.f;
#pragma unroll 8
        for (int e = 0; e < 128; e++) sk += tb2[e] * fw1[(128 + e) * HIDD + d];
        g_bk[d] = sk + fb1[d];
    }
}

// ============================================================================
// K2: 96 blocks. 0-31 u-L2 | 32-95 t-L2   (K=128, relu)
// ============================================================================
__global__ __launch_bounds__(256) void k_stage2(
    const float* __restrict__ uw1, const float* __restrict__ ub1,
    const float* __restrict__ tw1, const float* __restrict__ tb1)
{
    __shared__ float As[16 * 68];
    __shared__ float Bs[16 * 64];
    int blk = blockIdx.x;
    if (blk < 32) {
        gemm_tile(g_u1, uw1, ub1, g_u2, 128, 128, (blk >> 1) * 64, (blk & 1) * 64, true, As, Bs);
    } else {
        int i = blk - 32;
        gemm_tile(g_t1, tw1, tb1, g_t2, 128, 128, (i >> 1) * 64, (i & 1) * 64, true, As, Bs);
    }
}

// ============================================================================
// K3: 192 blocks. 0-63 u-L3 (uq) | 64-191 t-L3 (kh)   (N=256, K=128, bias)
// ============================================================================
__global__ __launch_bounds__(256) void k_stage3()
{
    __shared__ float As[16 * 68];
    __shared__ float Bs[16 * 64];
    int blk = blockIdx.x;
    if (blk < 64) {
        gemm_tile(g_u2, g_Wq, g_bq, g_uq, 256, 128, (blk >> 2) * 64, (blk & 3) * 64, false, As, Bs);
    } else {
        int i = blk - 64;
        gemm_tile(g_t2, g_Wk, g_bk, g_kh, 256, 128, (i >> 2) * 64, (i & 3) * 64, false, As, Bs);
    }
}

// ============================================================================
// final v3: logits[b,h,u,t] = fb2 + sum_d relu(uq[b,u,d]+hq[h,d]+kh[b,t,d])*fw2[d]
// grid (2, H, B) = 128 blocks, 512 threads.
// Whole (32u x 128t x 256d) problem resident in dynamic smem; ONE sync before
// the d-loop. In-block d-split: warps 0-7 do d[0,128), warps 8-15 d[128,256),
// each warp-set owns a 4u x 4t packed-f32x2 register tile; combine via smem.
// k rows stride 258 floats (129 8B-words == 1 mod 32) -> LDS.64 conflict-free.
// ============================================================================
#define KS_STRIDE 258
#define SMEM_FLOATS (128 * KS_STRIDE + 32 * 256 + 256 + 32 * 128)
#define SMEM_BYTES (SMEM_FLOATS * 4)

__global__ __launch_bounds__(512) void final_kernel(
    const float* __restrict__ fw2, const float* __restrict__ fb2,
    float* __restrict__ out)
{
    extern __shared__ float sm[];
    float* ks = sm;                          // [128][258]
    float* qs = sm + 128 * KS_STRIDE;        // [32][256]
    float* ws = qs + 32 * 256;               // [256]
    float* ps = ws + 256;                    // [32][128] partials (d-high half)

    int b = blockIdx.z, h = blockIdx.y, ut = blockIdx.x;
    int tid = threadIdx.x, lane = tid & 31, wrp = tid >> 5;

    const float* khp = g_kh + b * T_SZ * HIDD;
    const float* uqp = g_uq + (b * U_SZ + ut * 32) * HIDD;
    const float* hq  = g_hq + h * HIDD;

    // ---- load k tile: 128t x 256d, t-major stride 258 ----
#pragma unroll
    for (int i = 0; i < 16; i++) {
        int f4 = tid + i * 512;
        int t = f4 >> 6, d4 = (f4 & 63) << 2;
        float4 v = *(const float4*)&khp[t * HIDD + d4];
        float* dst = &ks[t * KS_STRIDE + d4];
        *(float2*)(dst)     = make_float2(v.x, v.y);
        *(float2*)(dst + 2) = make_float2(v.z, v.w);
    }
    // ---- load q tile (+ per-head query): 32u x 256d ----
#pragma unroll
    for (int i = 0; i < 4; i++) {
        int f4 = tid + i * 512;
        int u = f4 >> 6, d4 = (f4 & 63) << 2;
        float4 v  = *(const float4*)&uqp[u * HIDD + d4];
        float4 hv = *(const float4*)&hq[d4];
        *(float4*)&qs[u * 256 + d4] =
            make_float4(v.x + hv.x, v.y + hv.y, v.z + hv.z, v.w + hv.w);
    }
    if (tid < 256) ws[tid] = fw2[tid];
    __syncthreads();

    int wset = wrp & 7;                 // 0..7 -> u-quad
    int dbase = (wrp >> 3) * 128;       // 0 or 128

    const float* qp0 = qs + (wset * 4 + 0) * 256 + dbase;
    const float* qp1 = qs + (wset * 4 + 1) * 256 + dbase;
    const float* qp2 = qs + (wset * 4 + 2) * 256 + dbase;
    const float* qp3 = qs + (wset * 4 + 3) * 256 + dbase;
    const float* kp0 = ks + (lane +  0) * KS_STRIDE + dbase;
    const float* kp1 = ks + (lane + 32) * KS_STRIDE + dbase;
    const float* kp2 = ks + (lane + 64) * KS_STRIDE + dbase;
    const float* kp3 = ks + (lane + 96) * KS_STRIDE + dbase;
    const float* wp  = ws + dbase;

    ull acc[4][4] = {};

#pragma unroll 4
    for (int d = 0; d < 128; d += 2) {
        ull W  = *(const ull*)(wp + d);
        ull Q0 = *(const ull*)(qp0 + d);
        ull Q1 = *(const ull*)(qp1 + d);
        ull Q2 = *(const ull*)(qp2 + d);
        ull Q3 = *(const ull*)(qp3 + d);
        ull K0 = *(const ull*)(kp0 + d);
        ull K1 = *(const ull*)(kp1 + d);
        ull K2 = *(const ull*)(kp2 + d);
        ull K3 = *(const ull*)(kp3 + d);

#define RELU_FMA(ACC, Q, K)                                 \
        {                                                   \
            ull s_, r_; float lo_, hi_;                     \
            ADD2(s_, Q, K);                                 \
            UNPACK2(lo_, hi_, s_);                          \
            lo_ = fmaxf(lo_, 0.f);                          \
            hi_ = fmaxf(hi_, 0.f);                          \
            PACK2(r_, lo_, hi_);                            \
            FMA2(ACC, r_, W, ACC);                          \
        }
        RELU_FMA(acc[0][0], Q0, K0); RELU_FMA(acc[0][1], Q0, K1);
        RELU_FMA(acc[0][2], Q0, K2); RELU_FMA(acc[0][3], Q0, K3);
        RELU_FMA(acc[1][0], Q1, K0); RELU_FMA(acc[1][1], Q1, K1);
        RELU_FMA(acc[1][2], Q1, K2); RELU_FMA(acc[1][3], Q1, K3);
        RELU_FMA(acc[2][0], Q2, K0); RELU_FMA(acc[2][1], Q2, K1);
        RELU_FMA(acc[2][2], Q2, K2); RELU_FMA(acc[2][3], Q2, K3);
        RELU_FMA(acc[3][0], Q3, K0); RELU_FMA(acc[3][1], Q3, K1);
        RELU_FMA(acc[3][2], Q3, K2); RELU_FMA(acc[3][3], Q3, K3);
#undef RELU_FMA
    }

    // collapse packed accumulators to scalar per-output sums
    float r[4][4];
#pragma unroll
    for (int i = 0; i < 4; i++)
#pragma unroll
        for (int j = 0; j < 4; j++) {
            float lo, hi;
            UNPACK2(lo, hi, acc[i][j]);
            r[i][j] = lo + hi;
        }

    // d-high warps publish partials
    if (wrp >= 8) {
#pragma unroll
        for (int i = 0; i < 4; i++)
#pragma unroll
            for (int j = 0; j < 4; j++)
                ps[(wset * 4 + i) * 128 + lane + 32 * j] = r[i][j];
    }
    __syncthreads();

    // d-low warps combine + store
    if (wrp < 8) {
        float bias = fb2[0];
#pragma unroll
        for (int i = 0; i < 4; i++) {
            int urow = (b * H_HEADS + h) * U_SZ + ut * 32 + wset * 4 + i;
            float* orow = out + urow * T_SZ;
#pragma unroll
            for (int j = 0; j < 4; j++) {
                int t = lane + 32 * j;
                orow[t] = r[i][j] + ps[(wset * 4 + i) * 128 + t] + bias;
            }
        }
    }
}

// ---------------- launch ----------------
extern "C" void kernel_launch(void* const* d_in, const int* in_sizes, int n_in,
                              void* d_out, int out_size)
{
    const float* uav    = (const float*)d_in[0];
    const float* task   = (const float*)d_in[1];
    const float* uw0    = (const float*)d_in[2];
    const float* ub0    = (const float*)d_in[3];
    const float* uw1    = (const float*)d_in[4];
    const float* ub1    = (const float*)d_in[5];
    const float* uw2    = (const float*)d_in[6];
    const float* ub2    = (const float*)d_in[7];
    const float* tw0    = (const float*)d_in[8];
    const float* tb0    = (const float*)d_in[9];
    const float* tw1    = (const float*)d_in[10];
    const float* tb1    = (const float*)d_in[11];
    const float* tw2    = (const float*)d_in[12];
    const float* tb2    = (const float*)d_in[13];
    const float* head_q = (const float*)d_in[14];
    const float* fw1    = (const float*)d_in[15];
    const float* fb1    = (const float*)d_in[16];
    const float* fw2    = (const float*)d_in[17];
    const float* fb2    = (const float*)d_in[18];
    float* out = (float*)d_out;

    static bool attr_set = false;
    if (!attr_set) {
        cudaFuncSetAttribute(final_kernel,
                             cudaFuncAttributeMaxDynamicSharedMemorySize, SMEM_BYTES);
        attr_set = true;
    }

    k_stage1<<<114, 256>>>(uav, task, uw0, ub0, tw0, tb0, uw2, tw2, fw1, ub2, tb2, head_q, fb1);
    k_stage2<<<96, 256>>>(uw1, ub1, tw1, tb1);
    k_stage3<<<192, 256>>>();
    final_kernel<<<dim3(2, H_HEADS, B_SZ), 512, SMEM_BYTES>>>(fw2, fb2, out);
}

// round 15
// speedup vs baseline: 3.2069x; 1.1877x over previous
#include <cuda_runtime.h>

#define H_HEADS 4
#define HIDD 256
#define B_SZ 16
#define U_SZ 64
#define T_SZ 128
#define E_DIM 128

typedef unsigned long long ull;

// ---------------- packed f32x2 helpers ----------------
#define ADD2(out, a, b) \
    asm("add.rn.f32x2 %0, %1, %2;" : "=l"(out) : "l"(a), "l"(b))
#define FMA2(out, a, b, c) \
    asm("fma.rn.f32x2 %0, %1, %2, %3;" : "=l"(out) : "l"(a), "l"(b), "l"(c))
#define UNPACK2(lo, hi, v) \
    asm("mov.b64 {%0, %1}, %2;" : "=f"(lo), "=f"(hi) : "l"(v))
#define PACK2(v, lo, hi) \
    asm("mov.b64 %0, {%1, %2};" : "=l"(v) : "f"(lo), "f"(hi))

// ---------------- scratch (device globals) ----------------
__device__ float g_u1[1024 * 128];
__device__ float g_u2[1024 * 128];
__device__ float g_uq[1024 * 256];
__device__ float g_t1[2048 * 128];
__device__ float g_t2[2048 * 128];
__device__ float g_kh[2048 * 256];
__device__ float g_Wq[128 * 256];
__device__ float g_Wk[128 * 256];
__device__ float g_bq[256];
__device__ float g_bk[256];
__device__ float g_hq[4 * 256];

// ---------------- 64x64 GEMM tile, double-buffered K-loop ----------------
// C[bm:+64, bn:+64] = op(A[.,K] @ B[.,N] + bias), K%16==0.
// Next K-tile is prefetched into registers while current tile computes.
__device__ __forceinline__ void gemm_tile(
    const float* __restrict__ A, const float* __restrict__ B,
    const float* __restrict__ bias, float* __restrict__ C,
    int N, int K, int bm, int bn, bool relu,
    float* As /*16*68*/, float* Bs /*16*64*/)
{
    int tid = threadIdx.x;
    int tm = (tid / 16) * 4, tn = (tid % 16) * 4;
    int arow = tid / 4, ak = (tid % 4) * 4;
    int brow = tid / 16, bcol = (tid % 16) * 4;

    float acc[4][4] = {};

    // preload tile 0
    {
        float4 av = *(const float4*)&A[(bm + arow) * K + ak];
        As[(ak + 0) * 68 + arow] = av.x;
        As[(ak + 1) * 68 + arow] = av.y;
        As[(ak + 2) * 68 + arow] = av.z;
        As[(ak + 3) * 68 + arow] = av.w;
        *(float4*)&Bs[brow * 64 + bcol] = *(const float4*)&B[brow * N + bn + bcol];
    }
    __syncthreads();

    for (int k0 = 0; k0 < K; k0 += 16) {
        bool more = (k0 + 16) < K;
        float4 an, bn2;
        if (more) {
            an  = *(const float4*)&A[(bm + arow) * K + k0 + 16 + ak];
            bn2 = *(const float4*)&B[(k0 + 16 + brow) * N + bn + bcol];
        }
#pragma unroll
        for (int k = 0; k < 16; k++) {
            float4 a = *(const float4*)&As[k * 68 + tm];
            float4 bv = *(const float4*)&Bs[k * 64 + tn];
            acc[0][0] += a.x * bv.x; acc[0][1] += a.x * bv.y; acc[0][2] += a.x * bv.z; acc[0][3] += a.x * bv.w;
            acc[1][0] += a.y * bv.x; acc[1][1] += a.y * bv.y; acc[1][2] += a.y * bv.z; acc[1][3] += a.y * bv.w;
            acc[2][0] += a.z * bv.x; acc[2][1] += a.z * bv.y; acc[2][2] += a.z * bv.z; acc[2][3] += a.z * bv.w;
            acc[3][0] += a.w * bv.x; acc[3][1] += a.w * bv.y; acc[3][2] += a.w * bv.z; acc[3][3] += a.w * bv.w;
        }
        __syncthreads();
        if (more) {
            As[(ak + 0) * 68 + arow] = an.x;
            As[(ak + 1) * 68 + arow] = an.y;
            As[(ak + 2) * 68 + arow] = an.z;
            As[(ak + 3) * 68 + arow] = an.w;
            *(float4*)&Bs[brow * 64 + bcol] = bn2;
            __syncthreads();
        }
    }

    float b0 = 0.f, b1 = 0.f, b2 = 0.f, b3 = 0.f;
    if (bias) {
        b0 = bias[bn + tn + 0]; b1 = bias[bn + tn + 1];
        b2 = bias[bn + tn + 2]; b3 = bias[bn + tn + 3];
    }
#pragma unroll
    for (int i = 0; i < 4; i++) {
        float4 o = make_float4(acc[i][0] + b0, acc[i][1] + b1, acc[i][2] + b2, acc[i][3] + b3);
        if (relu) {
            o.x = fmaxf(o.x, 0.f); o.y = fmaxf(o.y, 0.f);
            o.z = fmaxf(o.z, 0.f); o.w = fmaxf(o.w, 0.f);
        }
        *(float4*)&C[(bm + tm + i) * N + bn + tn] = o;
    }
}

// ============================================================================
// K1: 96 blocks, pure L1 (K=32): 0-31 u-L1 | 32-95 t-L1
// ============================================================================
__global__ __launch_bounds__(256) void k_stage1(
    const float* __restrict__ uav, const float* __restrict__ task,
    const float* __restrict__ uw0, const float* __restrict__ ub0,
    const float* __restrict__ tw0, const float* __restrict__ tb0)
{
    __shared__ float As[16 * 68];
    __shared__ float Bs[16 * 64];
    int blk = blockIdx.x;
    if (blk < 32) {
        gemm_tile(uav, uw0, ub0, g_u1, 128, 32, (blk >> 1) * 64, (blk & 1) * 64, true, As, Bs);
    } else {
        int i = blk - 32;
        gemm_tile(task, tw0, tb0, g_t1, 128, 32, (i >> 1) * 64, (i & 1) * 64, true, As, Bs);
    }
}

// ============================================================================
// K2: 114 blocks. 0-31 u-L2 | 32-95 t-L2 | 96-103 Wq fold | 104-111 Wk fold
//     112: bq + hq[4]   113: bk(+fb1)       (folds needed only by K3)
// ============================================================================
__global__ __launch_bounds__(256) void k_stage2(
    const float* __restrict__ uw1, const float* __restrict__ ub1,
    const float* __restrict__ tw1, const float* __restrict__ tb1,
    const float* __restrict__ uw2, const float* __restrict__ tw2,
    const float* __restrict__ fw1, const float* __restrict__ ub2,
    const float* __restrict__ tb2, const float* __restrict__ head_q,
    const float* __restrict__ fb1)
{
    __shared__ float As[16 * 68];
    __shared__ float Bs[16 * 64];
    int blk = blockIdx.x;
    if (blk < 32) {
        gemm_tile(g_u1, uw1, ub1, g_u2, 128, 128, (blk >> 1) * 64, (blk & 1) * 64, true, As, Bs);
    } else if (blk < 96) {
        int i = blk - 32;
        gemm_tile(g_t1, tw1, tb1, g_t2, 128, 128, (i >> 1) * 64, (i & 1) * 64, true, As, Bs);
    } else if (blk < 104) {
        int i = blk - 96;
        gemm_tile(uw2, fw1, nullptr, g_Wq, 256, 128, (i >> 2) * 64, (i & 3) * 64, false, As, Bs);
    } else if (blk < 112) {
        int i = blk - 104;
        gemm_tile(tw2, fw1 + 128 * 256, nullptr, g_Wk, 256, 128, (i >> 2) * 64, (i & 3) * 64, false, As, Bs);
    } else if (blk == 112) {
        int d = threadIdx.x;
        float sq = 0.f, h0 = 0.f, h1 = 0.f, h2 = 0.f, h3 = 0.f;
#pragma unroll 8
        for (int e = 0; e < 128; e++) {
            float fq = fw1[e * HIDD + d];
            sq += ub2[e] * fq;
            h0 += head_q[e] * fq;
            h1 += head_q[128 + e] * fq;
            h2 += head_q[256 + e] * fq;
            h3 += head_q[384 + e] * fq;
        }
        g_bq[d] = sq;
        g_hq[d] = h0; g_hq[256 + d] = h1; g_hq[512 + d] = h2; g_hq[768 + d] = h3;
    } else {
        int d = threadIdx.x;
        float sk = 0.f;
#pragma unroll 8
        for (int e = 0; e < 128; e++) sk += tb2[e] * fw1[(128 + e) * HIDD + d];
        g_bk[d] = sk + fb1[d];
    }
}

// ============================================================================
// K3: 192 blocks. 0-63 u-L3 (uq) | 64-191 t-L3 (kh)   (N=256, K=128, bias)
// ============================================================================
__global__ __launch_bounds__(256) void k_stage3()
{
    __shared__ float As[16 * 68];
    __shared__ float Bs[16 * 64];
    int blk = blockIdx.x;
    if (blk < 64) {
        gemm_tile(g_u2, g_Wq, g_bq, g_uq, 256, 128, (blk >> 2) * 64, (blk & 3) * 64, false, As, Bs);
    } else {
        int i = blk - 64;
        gemm_tile(g_t2, g_Wk, g_bk, g_kh, 256, 128, (i >> 2) * 64, (i & 3) * 64, false, As, Bs);
    }
}

// ============================================================================
// final v4: logits[b,h,u,t] = fb2 + sum_d relu(uq[b,u,d]+hq[h,d]+kh[b,t,d])*fw2[d]
// grid (2, H, B) = 128 blocks, 512 threads.
// 4-way d-split: warp-quarter q owns d in [q*64, q*64+64). Thread tile 8u x 4t
// (32 packed f32x2 accumulators). Per iter: 13 LDS.64 feed 128 flop instrs.
// Quarters 1-3 publish partials to smem; quarter 0 combines + stores.
// k rows stride 258 floats (129 words == 1 mod 32) -> LDS.64 conflict-free.
// ============================================================================
#define KS_STRIDE 258
#define SMEM_FLOATS (128 * KS_STRIDE + 32 * 256 + 256 + 3 * 32 * 128)
#define SMEM_BYTES (SMEM_FLOATS * 4)

__global__ __launch_bounds__(512) void final_kernel(
    const float* __restrict__ fw2, const float* __restrict__ fb2,
    float* __restrict__ out)
{
    extern __shared__ float sm[];
    float* ks = sm;                          // [128][258]
    float* qs = sm + 128 * KS_STRIDE;        // [32][256]
    float* ws = qs + 32 * 256;               // [256]
    float* ps = ws + 256;                    // [3][32][128] partials

    int b = blockIdx.z, h = blockIdx.y, ut = blockIdx.x;
    int tid = threadIdx.x, lane = tid & 31, wrp = tid >> 5;

    const float* khp = g_kh + b * T_SZ * HIDD;
    const float* uqp = g_uq + (b * U_SZ + ut * 32) * HIDD;
    const float* hq  = g_hq + h * HIDD;

    // ---- load k tile: 128t x 256d, t-major stride 258 ----
#pragma unroll
    for (int i = 0; i < 16; i++) {
        int f4 = tid + i * 512;
        int t = f4 >> 6, d4 = (f4 & 63) << 2;
        float4 v = *(const float4*)&khp[t * HIDD + d4];
        float* dst = &ks[t * KS_STRIDE + d4];
        *(float2*)(dst)     = make_float2(v.x, v.y);
        *(float2*)(dst + 2) = make_float2(v.z, v.w);
    }
    // ---- load q tile (+ per-head query): 32u x 256d ----
#pragma unroll
    for (int i = 0; i < 4; i++) {
        int f4 = tid + i * 512;
        int u = f4 >> 6, d4 = (f4 & 63) << 2;
        float4 v  = *(const float4*)&uqp[u * HIDD + d4];
        float4 hv = *(const float4*)&hq[d4];
        *(float4*)&qs[u * 256 + d4] =
            make_float4(v.x + hv.x, v.y + hv.y, v.z + hv.z, v.w + hv.w);
    }
    if (tid < 256) ws[tid] = fw2[tid];
    __syncthreads();

    int quarter = wrp >> 2;            // 0..3 -> d segment
    int wq = wrp & 3;                  // 0..3 -> u octet
    int dbase = quarter * 64;
    int ubase = wq * 8;

    const float* wp = ws + dbase;
    const float* qp = qs + ubase * 256 + dbase;
    const float* kp = ks + lane * KS_STRIDE + dbase;

    ull acc[8][4] = {};

#pragma unroll 1
    for (int d = 0; d < 64; d += 2) {
        ull W = *(const ull*)(wp + d);
        ull Q[8], K[4];
#pragma unroll
        for (int u = 0; u < 8; u++) Q[u] = *(const ull*)(qp + u * 256 + d);
#pragma unroll
        for (int j = 0; j < 4; j++) K[j] = *(const ull*)(kp + j * 32 * KS_STRIDE + d);

#define RELU_FMA(ACC, QV, KV)                               \
        {                                                   \
            ull s_, r_; float lo_, hi_;                     \
            ADD2(s_, QV, KV);                               \
            UNPACK2(lo_, hi_, s_);                          \
            lo_ = fmaxf(lo_, 0.f);                          \
            hi_ = fmaxf(hi_, 0.f);                          \
            PACK2(r_, lo_, hi_);                            \
            FMA2(ACC, r_, W, ACC);                          \
        }
#pragma unroll
        for (int u = 0; u < 8; u++) {
            RELU_FMA(acc[u][0], Q[u], K[0]);
            RELU_FMA(acc[u][1], Q[u], K[1]);
            RELU_FMA(acc[u][2], Q[u], K[2]);
            RELU_FMA(acc[u][3], Q[u], K[3]);
        }
#undef RELU_FMA
    }

    // collapse packed accumulators
    float r[8][4];
#pragma unroll
    for (int u = 0; u < 8; u++)
#pragma unroll
        for (int j = 0; j < 4; j++) {
            float lo, hi;
            UNPACK2(lo, hi, acc[u][j]);
            r[u][j] = lo + hi;
        }

    if (quarter != 0) {
        float* pq = ps + (quarter - 1) * 32 * 128;
#pragma unroll
        for (int u = 0; u < 8; u++)
#pragma unroll
            for (int j = 0; j < 4; j++)
                pq[(ubase + u) * 128 + lane + 32 * j] = r[u][j];
    }
    __syncthreads();

    if (quarter == 0) {
        float bias = fb2[0];
#pragma unroll
        for (int u = 0; u < 8; u++) {
            int urow = (b * H_HEADS + h) * U_SZ + ut * 32 + ubase + u;
            float* orow = out + urow * T_SZ;
            int po = (ubase + u) * 128;
#pragma unroll
            for (int j = 0; j < 4; j++) {
                int t = lane + 32 * j;
                orow[t] = r[u][j] + ps[po + t] + ps[4096 + po + t]
                        + ps[8192 + po + t] + bias;
            }
        }
    }
}

// ---------------- launch ----------------
extern "C" void kernel_launch(void* const* d_in, const int* in_sizes, int n_in,
                              void* d_out, int out_size)
{
    const float* uav    = (const float*)d_in[0];
    const float* task   = (const float*)d_in[1];
    const float* uw0    = (const float*)d_in[2];
    const float* ub0    = (const float*)d_in[3];
    const float* uw1    = (const float*)d_in[4];
    const float* ub1    = (const float*)d_in[5];
    const float* uw2    = (const float*)d_in[6];
    const float* ub2    = (const float*)d_in[7];
    const float* tw0    = (const float*)d_in[8];
    const float* tb0    = (const float*)d_in[9];
    const float* tw1    = (const float*)d_in[10];
    const float* tb1    = (const float*)d_in[11];
    const float* tw2    = (const float*)d_in[12];
    const float* tb2    = (const float*)d_in[13];
    const float* head_q = (const float*)d_in[14];
    const float* fw1    = (const float*)d_in[15];
    const float* fb1    = (const float*)d_in[16];
    const float* fw2    = (const float*)d_in[17];
    const float* fb2    = (const float*)d_in[18];
    float* out = (float*)d_out;

    static bool attr_set = false;
    if (!attr_set) {
        cudaFuncSetAttribute(final_kernel,
                             cudaFuncAttributeMaxDynamicSharedMemorySize, SMEM_BYTES);
        attr_set = true;
    }

    k_stage1<<<96, 256>>>(uav, task, uw0, ub0, tw0, tb0);
    k_stage2<<<114, 256>>>(uw1, ub1, tw1, tb1, uw2, tw2, fw1, ub2, tb2, head_q, fb1);
    k_stage3<<<192, 256>>>();
    final_kernel<<<dim3(2, H_HEADS, B_SZ), 512, SMEM_BYTES>>>(fw2, fb2, out);
}